// round 15
// baseline (speedup 1.0000x reference)
#include <cuda_runtime.h>
#include <cuda_fp16.h>
#include <cstdint>

// GRU cell B=8192, I=H=1024 fp32. mma.sync fp16 m16n8k16 (fp32 accum).
// R15: fused zr+ht. ht role reshaped to the zr-throughput shape:
// block 128x128, warp 32x64 -> 16 MMAs per fragment burst (zr measured
// 393 TMAC/s at this shape vs 291-316 for 8-MMA-burst ht bodies).
// Both roles: 64KB smem, 2 CTA/SM. Flags/spin validated R13/R14. perm = R12.

#define BB 8192
#define HH 1024
#define KK 1024

__device__ __align__(16) uint4 g_xp[BB * KK / 8];
__device__ __align__(16) uint4 g_hp[BB * KK / 8];
__device__ __align__(16) uint4 g_rhp[BB * KK / 8];
__device__ __align__(16) float g_Z[BB * HH];
__device__ __align__(16) uint2 g_Wh[6][HH * KK / 4];  // 0:Wwz 1:Wuz 2:Wwr 3:Wur 4:Wu 5:Ww
__device__ int g_flag[64];

__device__ __forceinline__ void cp_async16(void* sdst, const void* gsrc) {
    uint32_t s = (uint32_t)__cvta_generic_to_shared(sdst);
    asm volatile("cp.async.cg.shared.global [%0], [%1], 16;\n" :: "r"(s), "l"(gsrc));
}
__device__ __forceinline__ void cp_commit() { asm volatile("cp.async.commit_group;\n"); }
__device__ __forceinline__ void cp_wait_all() { asm volatile("cp.async.wait_group 0;\n"); }

__device__ __forceinline__ void mma16(float c[4], const uint4& a, const uint2& b) {
    asm volatile(
        "mma.sync.aligned.m16n8k16.row.col.f32.f16.f16.f32 "
        "{%0,%1,%2,%3},{%4,%5,%6,%7},{%8,%9},{%0,%1,%2,%3};\n"
        : "+f"(c[0]), "+f"(c[1]), "+f"(c[2]), "+f"(c[3])
        : "r"(a.x), "r"(a.y), "r"(a.z), "r"(a.w), "r"(b.x), "r"(b.y));
}
__device__ __forceinline__ float sig_(float v) { return 1.0f / (1.0f + __expf(-v)); }
__device__ __forceinline__ float ftanh_(float v) {
    return 1.0f - 2.0f / (1.0f + __expf(2.0f * v));
}
__device__ __forceinline__ uint32_t h2u(float a, float b) {
    __half2 h = __floats2half2_rn(a, b);
    return *reinterpret_cast<uint32_t*>(&h);
}

// ---------------------------------------------------------------------------
// Preprocess (R12): smem-transposed, coalesced loads AND stores, 1D grid.
// ---------------------------------------------------------------------------
__global__ void __launch_bounds__(256) perm_all(
    const float* __restrict__ x, const float* __restrict__ hm,
    const float* __restrict__ w0, const float* __restrict__ w1,
    const float* __restrict__ w2, const float* __restrict__ w3,
    const float* __restrict__ w4, const float* __restrict__ w5) {
    __shared__ uint32_t sm[8 * 33 * 4];
    const int b = blockIdx.x;
    const int t = threadIdx.x;

    if (b < 8192) {
        const float* src = (b & 4096) ? hm : x;
        uint4* dst = (b & 4096) ? g_hp : g_xp;
        const int rb = (b >> 3) & 511, kbc = b & 7;
        const float4* s = reinterpret_cast<const float4*>(src + (rb * 16) * KK + kbc * 128);
        #pragma unroll
        for (int i = 0; i < 2; i++) {
            int f = t + i * 256;
            int row = f >> 5, c4 = f & 31;
            float4 v = s[row * 256 + c4];
            uint32_t p0 = h2u(v.x, v.y);
            uint32_t p1 = h2u(v.z, v.w);
            int g_ = row & 7, cr = row >> 3;
            int cp0 = c4 * 2;
            int kb0 = cp0 >> 3, j0 = cp0 & 7;
            sm[((kb0 * 33) + g_ * 4 + (j0 & 3)) * 4 + cr + 2 * (j0 >> 2)] = p0;
            int cp1 = cp0 + 1;
            int kb1 = cp1 >> 3, j1 = cp1 & 7;
            sm[((kb1 * 33) + g_ * 4 + (j1 & 3)) * 4 + cr + 2 * (j1 >> 2)] = p1;
        }
        __syncthreads();
        {
            int kb = t >> 5, lane = t & 31;
            dst[(rb * 64 + kbc * 8 + kb) * 32 + lane] =
                reinterpret_cast<const uint4*>(sm)[kb * 33 + lane];
        }
    } else {
        const int wb = b - 8192;
        const int widx = wb >> 10;
        const int bb = wb & 1023;
        const int nb = bb >> 3, kbc = bb & 7;
        const float* srcs[6] = {w0, w1, w2, w3, w4, w5};
        const float4* s = reinterpret_cast<const float4*>(srcs[widx] + (nb * 8) * KK + kbc * 128);
        {
            int f = t;
            int row = f >> 5, c4 = f & 31;
            float4 v = s[row * 256 + c4];
            uint32_t p0 = h2u(v.x, v.y);
            uint32_t p1 = h2u(v.z, v.w);
            int cp0 = c4 * 2;
            int kb0 = cp0 >> 3, j0 = cp0 & 7;
            sm[(kb0 * 33 + row * 4 + (j0 & 3)) * 2 + (j0 >> 2)] = p0;
            int cp1 = cp0 + 1;
            int kb1 = cp1 >> 3, j1 = cp1 & 7;
            sm[(kb1 * 33 + row * 4 + (j1 & 3)) * 2 + (j1 >> 2)] = p1;
        }
        __syncthreads();
        {
            int kb = t >> 5, lane = t & 31;
            g_Wh[widx][(nb * 64 + kbc * 8 + kb) * 32 + lane] =
                reinterpret_cast<const uint2*>(sm)[kb * 33 + lane];
        }
    }
}

// ---------------------------------------------------------------------------
// Fused GEMM kernel, 1536 CTAs, 64KB smem, 2 CTAs/SM.
//  bids [0,1024):    zr role, block 128x64,  bm=(bid>>4)*128, bn=(bid&15)*64
//  bids [1024,1536): ht role, block 128x128, bm=(idx>>3)*128, bn=(idx&7)*128
// ---------------------------------------------------------------------------
__global__ void __launch_bounds__(256, 2) gru_fused(const float* __restrict__ h,
                                                    float* __restrict__ out) {
    extern __shared__ uint4 sm4[];
    const int tid = threadIdx.x, wid = tid >> 5, lane = tid & 31;
    const int g = lane >> 2, tq = lane & 3;
    const int bid = blockIdx.x;

    if (bid < 1024) {
        // ================= zr role (R7 zr body, 2-stage 64KB) =================
        const int bm = (bid >> 4) * 128, bn = (bid & 15) * 64;
        const int rb0 = bm >> 4, nb0 = bn >> 3;

        auto stage = [&](int t, int buf) {
            const int seg = t >> 4, kb = (t & 15) * 4;
            const uint4* Ag = seg ? g_hp : g_xp;
            const uint4* Bz = reinterpret_cast<const uint4*>(g_Wh[seg ? 1 : 0]);
            const uint4* Br = reinterpret_cast<const uint4*>(g_Wh[seg ? 3 : 2]);
            #pragma unroll
            for (int i = 0; i < 4; i++) {
                int c = tid + i * 256, rbl = c >> 7, rem = c & 127;
                cp_async16(&sm4[buf * 1024 + rbl * 128 + rem],
                           &Ag[((rb0 + rbl) * 64 + kb) * 32 + rem]);
            }
            #pragma unroll
            for (int i = 0; i < 2; i++) {
                int c = tid + i * 256, nbl = c >> 6, rem = c & 63;
                int so = ((nb0 + nbl) * 64 + kb) * 16 + rem;
                cp_async16(&sm4[2048 + buf * 512 + nbl * 64 + rem], &Bz[so]);
                cp_async16(&sm4[3072 + buf * 512 + nbl * 64 + rem], &Br[so]);
            }
            cp_commit();
        };

        float accZ[2][4][4] = {}, accR[2][4][4] = {};
        stage(0, 0);

        const int r0 = (wid & 3) * 2, nbl = (wid >> 2) * 4;
        for (int t = 0; t < 32; t++) {
            cp_wait_all();
            __syncthreads();
            if (t + 1 < 32) stage(t + 1, (t + 1) & 1);
            const int buf = t & 1;
            const uint4* A_ = &sm4[buf * 1024];
            const uint2* Bz_ = reinterpret_cast<const uint2*>(&sm4[2048 + buf * 512]);
            const uint2* Br_ = reinterpret_cast<const uint2*>(&sm4[3072 + buf * 512]);
            #pragma unroll
            for (int kk = 0; kk < 4; kk++) {
                uint4 a0 = A_[(r0 * 4 + kk) * 32 + lane];
                uint4 a1 = A_[((r0 + 1) * 4 + kk) * 32 + lane];
                #pragma unroll
                for (int nt = 0; nt < 4; nt++) {
                    uint2 bz = Bz_[(nbl + nt) * 128 + kk * 32 + lane];
                    uint2 br = Br_[(nbl + nt) * 128 + kk * 32 + lane];
                    mma16(accZ[0][nt], a0, bz);
                    mma16(accZ[1][nt], a1, bz);
                    mma16(accR[0][nt], a0, br);
                    mma16(accR[1][nt], a1, br);
                }
            }
            __syncthreads();
        }

        uint32_t* rhp32 = reinterpret_cast<uint32_t*>(g_rhp);
        const int wm = (wid & 3) * 32, wn = (wid >> 2) * 32;
        #pragma unroll
        for (int mt = 0; mt < 2; mt++) {
            const int rbase = bm + wm + mt * 16;
            #pragma unroll
            for (int nt = 0; nt < 4; nt++) {
                const int colb = bn + wn + nt * 8 + tq * 2;
                const int kb = ((bn + wn) >> 4) + (nt >> 1);
                #pragma unroll
                for (int half = 0; half < 2; half++) {
                    const int row = rbase + half * 8 + g;
                    const int idx = row * HH + colb;
                    float2 hv = *reinterpret_cast<const float2*>(&h[idx]);
                    float2 zo;
                    zo.x = sig_(accZ[mt][nt][half * 2]);
                    zo.y = sig_(accZ[mt][nt][half * 2 + 1]);
                    *reinterpret_cast<float2*>(&g_Z[idx]) = zo;
                    float rh0 = sig_(accR[mt][nt][half * 2]) * hv.x;
                    float rh1 = sig_(accR[mt][nt][half * 2 + 1]) * hv.y;
                    const int rbm = (rbase >> 4);
                    const int regidx = half + 2 * (nt & 1);
                    rhp32[((rbm * 64 + kb) * 32 + lane) * 4 + regidx] = h2u(rh0, rh1);
                }
            }
        }

        __threadfence();
        __syncthreads();
        if (tid == 0) atomicAdd(&g_flag[bid >> 4], 1);
    } else {
        // ===== ht role (zr-shaped): block 128x128, 8 warps (4m x 2n),
        // ===== warp 32x64 -> 16 MMAs per kk burst. 2-stage, 64KB.
        const int idx0 = bid - 1024;
        const int bm = (idx0 >> 3) * 128, bn = (idx0 & 7) * 128;
        const int mblk = idx0 >> 3;

        if (tid == 0) {
            int v;
            do {
                asm volatile("ld.global.cg.s32 %0, [%1];" : "=r"(v) : "l"(&g_flag[mblk]));
            } while (v < 16);
        }
        __syncthreads();
        __threadfence();

        const int rb0 = bm >> 4, nb0 = bn >> 3;
        const int mrow = wid & 3, ncol = wid >> 2;   // 4m x 2n warps, warp 32x64

        auto stage = [&](int t, int buf) {
            const int seg = t >> 4, kb0 = (t & 15) * 4;
            const uint4* Ag = seg ? g_xp : g_rhp;
            const uint4* Bg = reinterpret_cast<const uint4*>(g_Wh[seg ? 5 : 4]);
            uint4* dst = &sm4[buf * 2048];
            #pragma unroll
            for (int i = 0; i < 4; i++) {
                int c = tid + i * 256, rbl = c >> 7, rem = c & 127;
                cp_async16(&dst[c], &Ag[((rb0 + rbl) * 64 + kb0) * 32 + rem]);
            }
            #pragma unroll
            for (int i = 0; i < 4; i++) {
                int c = tid + i * 256, nbl = c >> 6, rem = c & 63;
                cp_async16(&dst[1024 + c], &Bg[((nb0 + nbl) * 64 + kb0) * 16 + rem]);
            }
            cp_commit();
        };

        float acc[2][8][4] = {};
        stage(0, 0);

        for (int t = 0; t < 32; t++) {
            cp_wait_all();
            __syncthreads();
            if (t + 1 < 32) stage(t + 1, (t + 1) & 1);
            const uint4* A_ = &sm4[(t & 1) * 2048];
            const uint2* B_ = reinterpret_cast<const uint2*>(&sm4[(t & 1) * 2048 + 1024]);
            #pragma unroll
            for (int kk = 0; kk < 4; kk++) {
                uint4 a0 = A_[((mrow * 2 + 0) * 4 + kk) * 32 + lane];
                uint4 a1 = A_[((mrow * 2 + 1) * 4 + kk) * 32 + lane];
                #pragma unroll
                for (int n = 0; n < 8; n++) {
                    uint2 b = B_[((ncol * 8 + n) * 4 + kk) * 32 + lane];
                    mma16(acc[0][n], a0, b);
                    mma16(acc[1][n], a1, b);
                }
            }
            __syncthreads();
        }

        #pragma unroll
        for (int r = 0; r < 2; r++) {
            const int rowbase = bm + mrow * 32 + r * 16;
            #pragma unroll
            for (int n = 0; n < 8; n++) {
                const int col = bn + ncol * 64 + n * 8 + tq * 2;
                #pragma unroll
                for (int half = 0; half < 2; half++) {
                    const int oidx = (rowbase + half * 8 + g) * HH + col;
                    float2 hv = *reinterpret_cast<const float2*>(&h[oidx]);
                    float2 zv = *reinterpret_cast<const float2*>(&g_Z[oidx]);
                    float2 ov;
                    ov.x = zv.x * hv.x + (1.0f - zv.x) * ftanh_(acc[r][n][half * 2]);
                    ov.y = zv.y * hv.y + (1.0f - zv.y) * ftanh_(acc[r][n][half * 2 + 1]);
                    *reinterpret_cast<float2*>(&out[oidx]) = ov;
                }
            }
        }
    }
}

// ---------------------------------------------------------------------------
extern "C" void kernel_launch(void* const* d_in, const int* in_sizes, int n_in,
                              void* d_out, int out_size) {
    const float* x   = (const float*)d_in[0];
    const float* h   = (const float*)d_in[1];
    const float* Wwz = (const float*)d_in[2];
    const float* Wuz = (const float*)d_in[3];
    const float* Wwr = (const float*)d_in[4];
    const float* Wur = (const float*)d_in[5];
    const float* Wu  = (const float*)d_in[6];
    const float* Ww  = (const float*)d_in[7];
    float* out = (float*)d_out;

    const int smem = 4096 * 16;   // 64 KB (both roles)
    cudaFuncSetAttribute(gru_fused, cudaFuncAttributeMaxDynamicSharedMemorySize, smem);

    void* flagp = nullptr;
    cudaGetSymbolAddress(&flagp, g_flag);
    cudaMemsetAsync(flagp, 0, 64 * sizeof(int));

    perm_all<<<14336, 256>>>(x, h, Wwz, Wuz, Wwr, Wur, Wu, Ww);
    gru_fused<<<1536, 256, smem>>>(h, out);
}

// round 16
// speedup vs baseline: 1.0249x; 1.0249x over previous
#include <cuda_runtime.h>
#include <cuda_fp16.h>
#include <cstdint>

// GRU cell B=8192, I=H=1024 fp32. mma.sync fp16 m16n8k16 (fp32 accum).
// R16: consolidation of measured-best components. GEMMs = R9 verbatim,
// perm = R12 (coalesced transpose), g_Z stored as fp16 (halves the z
// round-trip traffic; z in [0,1] so fp16 adds <=2.4e-4 rel perturbation).

#define BB 8192
#define HH 1024
#define KK 1024

__device__ __align__(16) uint4 g_xp[BB * KK / 8];
__device__ __align__(16) uint4 g_hp[BB * KK / 8];
__device__ __align__(16) uint4 g_rhp[BB * KK / 8];
__device__ __align__(16) __half g_Z[BB * HH];
__device__ __align__(16) uint2 g_Wh[6][HH * KK / 4];  // 0:Wwz 1:Wuz 2:Wwr 3:Wur 4:Wu 5:Ww

__device__ __forceinline__ void cp_async16(void* sdst, const void* gsrc) {
    uint32_t s = (uint32_t)__cvta_generic_to_shared(sdst);
    asm volatile("cp.async.cg.shared.global [%0], [%1], 16;\n" :: "r"(s), "l"(gsrc));
}
__device__ __forceinline__ void cp_commit() { asm volatile("cp.async.commit_group;\n"); }
__device__ __forceinline__ void cp_wait1() { asm volatile("cp.async.wait_group 1;\n"); }
__device__ __forceinline__ void cp_wait0() { asm volatile("cp.async.wait_group 0;\n"); }

__device__ __forceinline__ void mma16(float c[4], const uint4& a, const uint2& b) {
    asm volatile(
        "mma.sync.aligned.m16n8k16.row.col.f32.f16.f16.f32 "
        "{%0,%1,%2,%3},{%4,%5,%6,%7},{%8,%9},{%0,%1,%2,%3};\n"
        : "+f"(c[0]), "+f"(c[1]), "+f"(c[2]), "+f"(c[3])
        : "r"(a.x), "r"(a.y), "r"(a.z), "r"(a.w), "r"(b.x), "r"(b.y));
}
__device__ __forceinline__ float sig_(float v) { return 1.0f / (1.0f + __expf(-v)); }
__device__ __forceinline__ float ftanh_(float v) {
    return 1.0f - 2.0f / (1.0f + __expf(2.0f * v));
}
__device__ __forceinline__ uint32_t h2u(float a, float b) {
    __half2 h = __floats2half2_rn(a, b);
    return *reinterpret_cast<uint32_t*>(&h);
}

// ---------------------------------------------------------------------------
// Preprocess (R12): smem-transposed, coalesced loads AND stores, 1D grid.
// ---------------------------------------------------------------------------
__global__ void __launch_bounds__(256) perm_all(
    const float* __restrict__ x, const float* __restrict__ hm,
    const float* __restrict__ w0, const float* __restrict__ w1,
    const float* __restrict__ w2, const float* __restrict__ w3,
    const float* __restrict__ w4, const float* __restrict__ w5) {
    __shared__ uint32_t sm[8 * 33 * 4];
    const int b = blockIdx.x;
    const int t = threadIdx.x;

    if (b < 8192) {
        const float* src = (b & 4096) ? hm : x;
        uint4* dst = (b & 4096) ? g_hp : g_xp;
        const int rb = (b >> 3) & 511, kbc = b & 7;
        const float4* s = reinterpret_cast<const float4*>(src + (rb * 16) * KK + kbc * 128);
        #pragma unroll
        for (int i = 0; i < 2; i++) {
            int f = t + i * 256;
            int row = f >> 5, c4 = f & 31;
            float4 v = s[row * 256 + c4];
            uint32_t p0 = h2u(v.x, v.y);
            uint32_t p1 = h2u(v.z, v.w);
            int g_ = row & 7, cr = row >> 3;
            int cp0 = c4 * 2;
            int kb0 = cp0 >> 3, j0 = cp0 & 7;
            sm[((kb0 * 33) + g_ * 4 + (j0 & 3)) * 4 + cr + 2 * (j0 >> 2)] = p0;
            int cp1 = cp0 + 1;
            int kb1 = cp1 >> 3, j1 = cp1 & 7;
            sm[((kb1 * 33) + g_ * 4 + (j1 & 3)) * 4 + cr + 2 * (j1 >> 2)] = p1;
        }
        __syncthreads();
        {
            int kb = t >> 5, lane = t & 31;
            dst[(rb * 64 + kbc * 8 + kb) * 32 + lane] =
                reinterpret_cast<const uint4*>(sm)[kb * 33 + lane];
        }
    } else {
        const int wb = b - 8192;
        const int widx = wb >> 10;
        const int bb = wb & 1023;
        const int nb = bb >> 3, kbc = bb & 7;
        const float* srcs[6] = {w0, w1, w2, w3, w4, w5};
        const float4* s = reinterpret_cast<const float4*>(srcs[widx] + (nb * 8) * KK + kbc * 128);
        {
            int f = t;
            int row = f >> 5, c4 = f & 31;
            float4 v = s[row * 256 + c4];
            uint32_t p0 = h2u(v.x, v.y);
            uint32_t p1 = h2u(v.z, v.w);
            int cp0 = c4 * 2;
            int kb0 = cp0 >> 3, j0 = cp0 & 7;
            sm[(kb0 * 33 + row * 4 + (j0 & 3)) * 2 + (j0 >> 2)] = p0;
            int cp1 = cp0 + 1;
            int kb1 = cp1 >> 3, j1 = cp1 & 7;
            sm[(kb1 * 33 + row * 4 + (j1 & 3)) * 2 + (j1 >> 2)] = p1;
        }
        __syncthreads();
        {
            int kb = t >> 5, lane = t & 31;
            g_Wh[widx][(nb * 64 + kbc * 8 + kb) * 32 + lane] =
                reinterpret_cast<const uint2*>(sm)[kb * 33 + lane];
        }
    }
}

// ---------------------------------------------------------------------------
// Kernel 1 (R9): dual-acc z/r GEMM. Block 128x64, 8 warps (4m x 2n),
// warp 32x32 dual, BK=64, 3-stage ring. 96KB smem, 2 CTAs/SM.
// Epilogue: z -> fp16 g_Z; rh -> fp16 fragment-ordered g_rhp.
// ---------------------------------------------------------------------------
__global__ void __launch_bounds__(256, 2) gemm_zr(const float* __restrict__ h) {
    extern __shared__ uint4 sm4[];
    const int tid = threadIdx.x, wid = tid >> 5, lane = tid & 31;
    const int g = lane >> 2, tq = lane & 3;
    const int bm = blockIdx.x * 128, bn = blockIdx.y * 64;
    const int rb0 = bm >> 4, nb0 = bn >> 3;

    auto stage = [&](int t) {
        const int seg = t >> 4, kb = (t & 15) * 4;
        const uint4* Ag = seg ? g_hp : g_xp;
        const uint4* Bz = reinterpret_cast<const uint4*>(g_Wh[seg ? 1 : 0]);
        const uint4* Br = reinterpret_cast<const uint4*>(g_Wh[seg ? 3 : 2]);
        uint4* dst = &sm4[(t % 3) * 2048];
        #pragma unroll
        for (int i = 0; i < 4; i++) {
            int c = tid + i * 256, rbl = c >> 7, rem = c & 127;
            cp_async16(&dst[c], &Ag[((rb0 + rbl) * 64 + kb) * 32 + rem]);
        }
        #pragma unroll
        for (int i = 0; i < 2; i++) {
            int c = tid + i * 256, nbl = c >> 6, rem = c & 63;
            int so = ((nb0 + nbl) * 64 + kb) * 16 + rem;
            cp_async16(&dst[1024 + c], &Bz[so]);
            cp_async16(&dst[1536 + c], &Br[so]);
        }
        cp_commit();
    };

    float accZ[2][4][4] = {}, accR[2][4][4] = {};
    stage(0);
    stage(1);

    const int r0 = (wid & 3) * 2, nbl = (wid >> 2) * 4;
    for (int t = 0; t < 32; t++) {
        if (t + 2 < 32) cp_wait1(); else cp_wait0();
        __syncthreads();
        if (t + 2 < 32) stage(t + 2);
        const uint4* A_ = &sm4[(t % 3) * 2048];
        const uint2* Bz_ = reinterpret_cast<const uint2*>(&A_[1024]);
        const uint2* Br_ = reinterpret_cast<const uint2*>(&A_[1536]);
        #pragma unroll
        for (int kk = 0; kk < 4; kk++) {
            uint4 a0 = A_[(r0 * 4 + kk) * 32 + lane];
            uint4 a1 = A_[((r0 + 1) * 4 + kk) * 32 + lane];
            #pragma unroll
            for (int nt = 0; nt < 4; nt++) {
                uint2 bz = Bz_[(nbl + nt) * 128 + kk * 32 + lane];
                uint2 br = Br_[(nbl + nt) * 128 + kk * 32 + lane];
                mma16(accZ[0][nt], a0, bz);
                mma16(accZ[1][nt], a1, bz);
                mma16(accR[0][nt], a0, br);
                mma16(accR[1][nt], a1, br);
            }
        }
    }

    // epilogue: z fp16; rh fp16 fragment-ordered
    uint32_t* rhp32 = reinterpret_cast<uint32_t*>(g_rhp);
    const int wm = (wid & 3) * 32, wn = (wid >> 2) * 32;
    #pragma unroll
    for (int mt = 0; mt < 2; mt++) {
        const int rbase = bm + wm + mt * 16;
        #pragma unroll
        for (int nt = 0; nt < 4; nt++) {
            const int colb = bn + wn + nt * 8 + tq * 2;
            const int kb = ((bn + wn) >> 4) + (nt >> 1);
            #pragma unroll
            for (int half = 0; half < 2; half++) {
                const int row = rbase + half * 8 + g;
                const int idx = row * HH + colb;
                float2 hv = *reinterpret_cast<const float2*>(&h[idx]);
                float z0 = sig_(accZ[mt][nt][half * 2]);
                float z1 = sig_(accZ[mt][nt][half * 2 + 1]);
                *reinterpret_cast<uint32_t*>(&g_Z[idx]) = h2u(z0, z1);
                float rh0 = sig_(accR[mt][nt][half * 2]) * hv.x;
                float rh1 = sig_(accR[mt][nt][half * 2 + 1]) * hv.y;
                const int rbm = (rbase >> 4);
                const int regidx = half + 2 * (nt & 1);
                rhp32[((rbm * 64 + kb) * 32 + lane) * 4 + regidx] = h2u(rh0, rh1);
            }
        }
    }
}

// ---------------------------------------------------------------------------
// Kernel 2 (R9): block 128x64, 8 warps (4m x 2n), warp 32x32, BK=64,
// 3-stage ring. 72KB smem, 3 CTAs/SM. Reads z from fp16 g_Z.
// ---------------------------------------------------------------------------
__global__ void __launch_bounds__(256, 3) gemm_ht(const float* __restrict__ h,
                                                  float* __restrict__ out) {
    extern __shared__ uint4 sm4[];
    const int tid = threadIdx.x, wid = tid >> 5, lane = tid & 31;
    const int g = lane >> 2, tq = lane & 3;
    const int mrow = wid & 3, ncol = wid >> 2;   // 4 x 2 warps, warp 32x32
    const int bm = blockIdx.x * 128, bn = blockIdx.y * 64;
    const int rb0 = bm >> 4, nb0 = bn >> 3;

    auto stage = [&](int t) {
        const int seg = t >> 4, kb0 = (t & 15) * 4;
        const uint4* Ag = seg ? g_xp : g_rhp;
        const uint4* Bg = reinterpret_cast<const uint4*>(g_Wh[seg ? 5 : 4]);
        uint4* dst = &sm4[(t % 3) * 1536];
        #pragma unroll
        for (int i = 0; i < 4; i++) {
            int c = tid + i * 256, rbl = c >> 7, rem = c & 127;
            cp_async16(&dst[c], &Ag[((rb0 + rbl) * 64 + kb0) * 32 + rem]);
        }
        #pragma unroll
        for (int i = 0; i < 2; i++) {
            int c = tid + i * 256, nbl = c >> 6, rem = c & 63;
            cp_async16(&dst[1024 + c], &Bg[((nb0 + nbl) * 64 + kb0) * 16 + rem]);
        }
        cp_commit();
    };

    float acc[2][4][4] = {};
    stage(0);
    stage(1);

    for (int t = 0; t < 32; t++) {
        if (t + 2 < 32) cp_wait1(); else cp_wait0();
        __syncthreads();
        if (t + 2 < 32) stage(t + 2);
        const uint4* A_ = &sm4[(t % 3) * 1536];
        const uint2* B_ = reinterpret_cast<const uint2*>(&A_[1024]);
        #pragma unroll
        for (int kk = 0; kk < 4; kk++) {
            uint4 a0 = A_[((mrow * 2 + 0) * 4 + kk) * 32 + lane];
            uint4 a1 = A_[((mrow * 2 + 1) * 4 + kk) * 32 + lane];
            #pragma unroll
            for (int n = 0; n < 4; n++) {
                uint2 b = B_[((ncol * 4 + n) * 4 + kk) * 32 + lane];
                mma16(acc[0][n], a0, b);
                mma16(acc[1][n], a1, b);
            }
        }
    }

    #pragma unroll
    for (int r = 0; r < 2; r++) {
        const int rowbase = bm + mrow * 32 + r * 16;
        #pragma unroll
        for (int n = 0; n < 4; n++) {
            const int col = bn + ncol * 32 + n * 8 + tq * 2;
            #pragma unroll
            for (int half = 0; half < 2; half++) {
                const int idx = (rowbase + half * 8 + g) * HH + col;
                float2 hv = *reinterpret_cast<const float2*>(&h[idx]);
                __half2 zh = *reinterpret_cast<const __half2*>(&g_Z[idx]);
                float2 zv = __half22float2(zh);
                float2 ov;
                ov.x = zv.x * hv.x + (1.0f - zv.x) * ftanh_(acc[r][n][half * 2]);
                ov.y = zv.y * hv.y + (1.0f - zv.y) * ftanh_(acc[r][n][half * 2 + 1]);
                *reinterpret_cast<float2*>(&out[idx]) = ov;
            }
        }
    }
}

// ---------------------------------------------------------------------------
extern "C" void kernel_launch(void* const* d_in, const int* in_sizes, int n_in,
                              void* d_out, int out_size) {
    const float* x   = (const float*)d_in[0];
    const float* h   = (const float*)d_in[1];
    const float* Wwz = (const float*)d_in[2];
    const float* Wuz = (const float*)d_in[3];
    const float* Wwr = (const float*)d_in[4];
    const float* Wur = (const float*)d_in[5];
    const float* Wu  = (const float*)d_in[6];
    const float* Ww  = (const float*)d_in[7];
    float* out = (float*)d_out;

    const int s1 = 6144 * 16;   // 96 KB
    const int s2 = 4608 * 16;   // 72 KB
    cudaFuncSetAttribute(gemm_zr, cudaFuncAttributeMaxDynamicSharedMemorySize, s1);
    cudaFuncSetAttribute(gemm_ht, cudaFuncAttributeMaxDynamicSharedMemorySize, s2);

    perm_all<<<14336, 256>>>(x, h, Wwz, Wuz, Wwr, Wur, Wu, Ww);
    gemm_zr<<<dim3(64, 16), 256, s1>>>(h);
    gemm_ht<<<dim3(64, 16), 256, s2>>>(h, out);
}

// round 17
// speedup vs baseline: 1.0377x; 1.0125x over previous
#include <cuda_runtime.h>
#include <cuda_fp16.h>
#include <cstdint>

// GRU cell B=8192, I=H=1024 fp32. mma.sync fp16 m16n8k16 (fp32 accum).
// R17: R16 + both GEMM epilogues read h from g_hp (fp16 fragment copy)
// instead of fp32 linear h — halves the epilogue h traffic. Fragment
// component algebra identical to the validated g_rhp store path.

#define BB 8192
#define HH 1024
#define KK 1024

__device__ __align__(16) uint4 g_xp[BB * KK / 8];
__device__ __align__(16) uint4 g_hp[BB * KK / 8];
__device__ __align__(16) uint4 g_rhp[BB * KK / 8];
__device__ __align__(16) __half g_Z[BB * HH];
__device__ __align__(16) uint2 g_Wh[6][HH * KK / 4];  // 0:Wwz 1:Wuz 2:Wwr 3:Wur 4:Wu 5:Ww

__device__ __forceinline__ void cp_async16(void* sdst, const void* gsrc) {
    uint32_t s = (uint32_t)__cvta_generic_to_shared(sdst);
    asm volatile("cp.async.cg.shared.global [%0], [%1], 16;\n" :: "r"(s), "l"(gsrc));
}
__device__ __forceinline__ void cp_commit() { asm volatile("cp.async.commit_group;\n"); }
__device__ __forceinline__ void cp_wait1() { asm volatile("cp.async.wait_group 1;\n"); }
__device__ __forceinline__ void cp_wait0() { asm volatile("cp.async.wait_group 0;\n"); }

__device__ __forceinline__ void mma16(float c[4], const uint4& a, const uint2& b) {
    asm volatile(
        "mma.sync.aligned.m16n8k16.row.col.f32.f16.f16.f32 "
        "{%0,%1,%2,%3},{%4,%5,%6,%7},{%8,%9},{%0,%1,%2,%3};\n"
        : "+f"(c[0]), "+f"(c[1]), "+f"(c[2]), "+f"(c[3])
        : "r"(a.x), "r"(a.y), "r"(a.z), "r"(a.w), "r"(b.x), "r"(b.y));
}
__device__ __forceinline__ float sig_(float v) { return 1.0f / (1.0f + __expf(-v)); }
__device__ __forceinline__ float ftanh_(float v) {
    return 1.0f - 2.0f / (1.0f + __expf(2.0f * v));
}
__device__ __forceinline__ uint32_t h2u(float a, float b) {
    __half2 h = __floats2half2_rn(a, b);
    return *reinterpret_cast<uint32_t*>(&h);
}
__device__ __forceinline__ float2 u2f(uint32_t u) {
    return __half22float2(*reinterpret_cast<__half2*>(&u));
}

// ---------------------------------------------------------------------------
// Preprocess (R12): smem-transposed, coalesced loads AND stores, 1D grid.
// ---------------------------------------------------------------------------
__global__ void __launch_bounds__(256) perm_all(
    const float* __restrict__ x, const float* __restrict__ hm,
    const float* __restrict__ w0, const float* __restrict__ w1,
    const float* __restrict__ w2, const float* __restrict__ w3,
    const float* __restrict__ w4, const float* __restrict__ w5) {
    __shared__ uint32_t sm[8 * 33 * 4];
    const int b = blockIdx.x;
    const int t = threadIdx.x;

    if (b < 8192) {
        const float* src = (b & 4096) ? hm : x;
        uint4* dst = (b & 4096) ? g_hp : g_xp;
        const int rb = (b >> 3) & 511, kbc = b & 7;
        const float4* s = reinterpret_cast<const float4*>(src + (rb * 16) * KK + kbc * 128);
        #pragma unroll
        for (int i = 0; i < 2; i++) {
            int f = t + i * 256;
            int row = f >> 5, c4 = f & 31;
            float4 v = s[row * 256 + c4];
            uint32_t p0 = h2u(v.x, v.y);
            uint32_t p1 = h2u(v.z, v.w);
            int g_ = row & 7, cr = row >> 3;
            int cp0 = c4 * 2;
            int kb0 = cp0 >> 3, j0 = cp0 & 7;
            sm[((kb0 * 33) + g_ * 4 + (j0 & 3)) * 4 + cr + 2 * (j0 >> 2)] = p0;
            int cp1 = cp0 + 1;
            int kb1 = cp1 >> 3, j1 = cp1 & 7;
            sm[((kb1 * 33) + g_ * 4 + (j1 & 3)) * 4 + cr + 2 * (j1 >> 2)] = p1;
        }
        __syncthreads();
        {
            int kb = t >> 5, lane = t & 31;
            dst[(rb * 64 + kbc * 8 + kb) * 32 + lane] =
                reinterpret_cast<const uint4*>(sm)[kb * 33 + lane];
        }
    } else {
        const int wb = b - 8192;
        const int widx = wb >> 10;
        const int bb = wb & 1023;
        const int nb = bb >> 3, kbc = bb & 7;
        const float* srcs[6] = {w0, w1, w2, w3, w4, w5};
        const float4* s = reinterpret_cast<const float4*>(srcs[widx] + (nb * 8) * KK + kbc * 128);
        {
            int f = t;
            int row = f >> 5, c4 = f & 31;
            float4 v = s[row * 256 + c4];
            uint32_t p0 = h2u(v.x, v.y);
            uint32_t p1 = h2u(v.z, v.w);
            int cp0 = c4 * 2;
            int kb0 = cp0 >> 3, j0 = cp0 & 7;
            sm[(kb0 * 33 + row * 4 + (j0 & 3)) * 2 + (j0 >> 2)] = p0;
            int cp1 = cp0 + 1;
            int kb1 = cp1 >> 3, j1 = cp1 & 7;
            sm[(kb1 * 33 + row * 4 + (j1 & 3)) * 2 + (j1 >> 2)] = p1;
        }
        __syncthreads();
        {
            int kb = t >> 5, lane = t & 31;
            g_Wh[widx][(nb * 64 + kbc * 8 + kb) * 32 + lane] =
                reinterpret_cast<const uint2*>(sm)[kb * 33 + lane];
        }
    }
}

// ---------------------------------------------------------------------------
// Kernel 1 (R9 mainloop): dual-acc z/r GEMM. Block 128x64, 8 warps (4m x 2n),
// warp 32x32 dual, BK=64, 3-stage ring. 96KB smem, 2 CTAs/SM.
// Epilogue: h from g_hp (fp16 frag); z -> fp16 g_Z; rh -> fp16 frag g_rhp.
// ---------------------------------------------------------------------------
__global__ void __launch_bounds__(256, 2) gemm_zr() {
    extern __shared__ uint4 sm4[];
    const int tid = threadIdx.x, wid = tid >> 5, lane = tid & 31;
    const int bm = blockIdx.x * 128, bn = blockIdx.y * 64;
    const int rb0 = bm >> 4, nb0 = bn >> 3;

    auto stage = [&](int t) {
        const int seg = t >> 4, kb = (t & 15) * 4;
        const uint4* Ag = seg ? g_hp : g_xp;
        const uint4* Bz = reinterpret_cast<const uint4*>(g_Wh[seg ? 1 : 0]);
        const uint4* Br = reinterpret_cast<const uint4*>(g_Wh[seg ? 3 : 2]);
        uint4* dst = &sm4[(t % 3) * 2048];
        #pragma unroll
        for (int i = 0; i < 4; i++) {
            int c = tid + i * 256, rbl = c >> 7, rem = c & 127;
            cp_async16(&dst[c], &Ag[((rb0 + rbl) * 64 + kb) * 32 + rem]);
        }
        #pragma unroll
        for (int i = 0; i < 2; i++) {
            int c = tid + i * 256, nbl = c >> 6, rem = c & 63;
            int so = ((nb0 + nbl) * 64 + kb) * 16 + rem;
            cp_async16(&dst[1024 + c], &Bz[so]);
            cp_async16(&dst[1536 + c], &Br[so]);
        }
        cp_commit();
    };

    float accZ[2][4][4] = {}, accR[2][4][4] = {};
    stage(0);
    stage(1);

    const int r0 = (wid & 3) * 2, nbl = (wid >> 2) * 4;
    for (int t = 0; t < 32; t++) {
        if (t + 2 < 32) cp_wait1(); else cp_wait0();
        __syncthreads();
        if (t + 2 < 32) stage(t + 2);
        const uint4* A_ = &sm4[(t % 3) * 2048];
        const uint2* Bz_ = reinterpret_cast<const uint2*>(&A_[1024]);
        const uint2* Br_ = reinterpret_cast<const uint2*>(&A_[1536]);
        #pragma unroll
        for (int kk = 0; kk < 4; kk++) {
            uint4 a0 = A_[(r0 * 4 + kk) * 32 + lane];
            uint4 a1 = A_[((r0 + 1) * 4 + kk) * 32 + lane];
            #pragma unroll
            for (int nt = 0; nt < 4; nt++) {
                uint2 bz = Bz_[(nbl + nt) * 128 + kk * 32 + lane];
                uint2 br = Br_[(nbl + nt) * 128 + kk * 32 + lane];
                mma16(accZ[0][nt], a0, bz);
                mma16(accZ[1][nt], a1, bz);
                mma16(accR[0][nt], a0, br);
                mma16(accR[1][nt], a1, br);
            }
        }
    }

    // epilogue: h from g_hp fragments; z fp16; rh fp16 fragment-ordered
    uint32_t* rhp32 = reinterpret_cast<uint32_t*>(g_rhp);
    const uint32_t* hp32 = reinterpret_cast<const uint32_t*>(g_hp);
    const int g = lane >> 2, tq = lane & 3;
    const int wm = (wid & 3) * 32, wn = (wid >> 2) * 32;
    #pragma unroll
    for (int mt = 0; mt < 2; mt++) {
        const int rbase = bm + wm + mt * 16;
        const int rbm = rbase >> 4;
        #pragma unroll
        for (int nt = 0; nt < 4; nt++) {
            const int colb = bn + wn + nt * 8 + tq * 2;
            const int kb = ((bn + wn) >> 4) + (nt >> 1);
            #pragma unroll
            for (int half = 0; half < 2; half++) {
                const int row = rbase + half * 8 + g;
                const int idx = row * HH + colb;
                const int regidx = half + 2 * (nt & 1);
                const int fidx = ((rbm * 64 + kb) * 32 + lane) * 4 + regidx;
                float2 hv = u2f(hp32[fidx]);
                float z0 = sig_(accZ[mt][nt][half * 2]);
                float z1 = sig_(accZ[mt][nt][half * 2 + 1]);
                *reinterpret_cast<uint32_t*>(&g_Z[idx]) = h2u(z0, z1);
                float rh0 = sig_(accR[mt][nt][half * 2]) * hv.x;
                float rh1 = sig_(accR[mt][nt][half * 2 + 1]) * hv.y;
                rhp32[fidx] = h2u(rh0, rh1);
            }
        }
    }
}

// ---------------------------------------------------------------------------
// Kernel 2 (R9 mainloop): block 128x64, 8 warps (4m x 2n), warp 32x32, BK=64,
// 3-stage ring. 72KB smem, 3 CTAs/SM. Epilogue: h from g_hp, z from fp16 g_Z.
// ---------------------------------------------------------------------------
__global__ void __launch_bounds__(256, 3) gemm_ht(float* __restrict__ out) {
    extern __shared__ uint4 sm4[];
    const int tid = threadIdx.x, wid = tid >> 5, lane = tid & 31;
    const int mrow = wid & 3, ncol = wid >> 2;   // 4 x 2 warps, warp 32x32
    const int bm = blockIdx.x * 128, bn = blockIdx.y * 64;
    const int rb0 = bm >> 4, nb0 = bn >> 3;

    auto stage = [&](int t) {
        const int seg = t >> 4, kb0 = (t & 15) * 4;
        const uint4* Ag = seg ? g_xp : g_rhp;
        const uint4* Bg = reinterpret_cast<const uint4*>(g_Wh[seg ? 5 : 4]);
        uint4* dst = &sm4[(t % 3) * 1536];
        #pragma unroll
        for (int i = 0; i < 4; i++) {
            int c = tid + i * 256, rbl = c >> 7, rem = c & 127;
            cp_async16(&dst[c], &Ag[((rb0 + rbl) * 64 + kb0) * 32 + rem]);
        }
        #pragma unroll
        for (int i = 0; i < 2; i++) {
            int c = tid + i * 256, nbl = c >> 6, rem = c & 63;
            cp_async16(&dst[1024 + c], &Bg[((nb0 + nbl) * 64 + kb0) * 16 + rem]);
        }
        cp_commit();
    };

    float acc[2][4][4] = {};
    stage(0);
    stage(1);

    for (int t = 0; t < 32; t++) {
        if (t + 2 < 32) cp_wait1(); else cp_wait0();
        __syncthreads();
        if (t + 2 < 32) stage(t + 2);
        const uint4* A_ = &sm4[(t % 3) * 1536];
        const uint2* B_ = reinterpret_cast<const uint2*>(&A_[1024]);
        #pragma unroll
        for (int kk = 0; kk < 4; kk++) {
            uint4 a0 = A_[((mrow * 2 + 0) * 4 + kk) * 32 + lane];
            uint4 a1 = A_[((mrow * 2 + 1) * 4 + kk) * 32 + lane];
            #pragma unroll
            for (int n = 0; n < 4; n++) {
                uint2 b = B_[((ncol * 4 + n) * 4 + kk) * 32 + lane];
                mma16(acc[0][n], a0, b);
                mma16(acc[1][n], a1, b);
            }
        }
    }

    const uint32_t* hp32 = reinterpret_cast<const uint32_t*>(g_hp);
    const int g = lane >> 2, tq = lane & 3;
    #pragma unroll
    for (int r = 0; r < 2; r++) {
        const int rowbase = bm + mrow * 32 + r * 16;
        const int rbm = rowbase >> 4;
        #pragma unroll
        for (int n = 0; n < 4; n++) {
            const int col = bn + ncol * 32 + n * 8 + tq * 2;
            const int kb = (bn >> 4) + ncol * 2 + (n >> 1);
            #pragma unroll
            for (int half = 0; half < 2; half++) {
                const int idx = (rowbase + half * 8 + g) * HH + col;
                const int fidx = ((rbm * 64 + kb) * 32 + lane) * 4 + (half + 2 * (n & 1));
                float2 hv = u2f(hp32[fidx]);
                __half2 zh = *reinterpret_cast<const __half2*>(&g_Z[idx]);
                float2 zv = __half22float2(zh);
                float2 ov;
                ov.x = zv.x * hv.x + (1.0f - zv.x) * ftanh_(acc[r][n][half * 2]);
                ov.y = zv.y * hv.y + (1.0f - zv.y) * ftanh_(acc[r][n][half * 2 + 1]);
                *reinterpret_cast<float2*>(&out[idx]) = ov;
            }
        }
    }
}

// ---------------------------------------------------------------------------
extern "C" void kernel_launch(void* const* d_in, const int* in_sizes, int n_in,
                              void* d_out, int out_size) {
    const float* x   = (const float*)d_in[0];
    const float* h   = (const float*)d_in[1];
    const float* Wwz = (const float*)d_in[2];
    const float* Wuz = (const float*)d_in[3];
    const float* Wwr = (const float*)d_in[4];
    const float* Wur = (const float*)d_in[5];
    const float* Wu  = (const float*)d_in[6];
    const float* Ww  = (const float*)d_in[7];
    float* out = (float*)d_out;

    const int s1 = 6144 * 16;   // 96 KB
    const int s2 = 4608 * 16;   // 72 KB
    cudaFuncSetAttribute(gemm_zr, cudaFuncAttributeMaxDynamicSharedMemorySize, s1);
    cudaFuncSetAttribute(gemm_ht, cudaFuncAttributeMaxDynamicSharedMemorySize, s2);

    perm_all<<<14336, 256>>>(x, h, Wwz, Wuz, Wwr, Wur, Wu, Ww);
    gemm_zr<<<dim3(64, 16), 256, s1>>>();
    gemm_ht<<<dim3(64, 16), 256, s2>>>(out);
}